// round 1
// baseline (speedup 1.0000x reference)
#include <cuda_runtime.h>
#include <math.h>

// Problem constants
#define BB 4
#define SS 2048
#define DD 1024
#define NH 16
#define HD 64

// Scratch: Q, K, V, Y_att each [B,S,D] fp32 (33.5 MB each)
__device__ float g_q[BB * SS * DD];
__device__ float g_k[BB * SS * DD];
__device__ float g_v[BB * SS * DD];
__device__ float g_y[BB * SS * DD];

// ---------------------------------------------------------------------------
// SGEMM-NT: C[m][n] = sum_k A[m][k] * B[n][k]
// Block tile 128x128, K-tile 16, 256 threads, 8x8 per-thread microtile.
// Smem stored k-major (transposed) with stride 132 to reduce bank conflicts
// and keep float4 alignment for the compute-phase reads.
// Requires: M%128==0, N%128==0, K%16==0, K%4==0 (float4 gmem loads).
// ---------------------------------------------------------------------------
__global__ void __launch_bounds__(256) sgemm_nt(const float* __restrict__ A,
                                                const float* __restrict__ B,
                                                float* __restrict__ C,
                                                int M, int N, int K)
{
    __shared__ float As[16][132];
    __shared__ float Bs[16][132];

    const int tid = threadIdx.x;
    const int tx  = tid & 15;       // 0..15
    const int ty  = tid >> 4;       // 0..15
    const int m0  = blockIdx.y * 128;
    const int n0  = blockIdx.x * 128;

    // gmem load mapping: 128 rows x 16 k = 2048 floats, 8 per thread (2x float4)
    const int lr = tid >> 2;        // 0..63 (rows lr and lr+64)
    const int lk = (tid & 3) << 2;  // 0,4,8,12

    float acc[8][8];
#pragma unroll
    for (int i = 0; i < 8; i++)
#pragma unroll
        for (int j = 0; j < 8; j++) acc[i][j] = 0.f;

    const float* Aptr = A + (size_t)(m0 + lr) * K + lk;
    const float* Bptr = B + (size_t)(n0 + lr) * K + lk;

    for (int k0 = 0; k0 < K; k0 += 16) {
#pragma unroll
        for (int r = 0; r < 2; r++) {
            const int row = lr + r * 64;
            float4 av = *(const float4*)(Aptr + (size_t)r * 64 * K + k0);
            As[lk + 0][row] = av.x;
            As[lk + 1][row] = av.y;
            As[lk + 2][row] = av.z;
            As[lk + 3][row] = av.w;
            float4 bv = *(const float4*)(Bptr + (size_t)r * 64 * K + k0);
            Bs[lk + 0][row] = bv.x;
            Bs[lk + 1][row] = bv.y;
            Bs[lk + 2][row] = bv.z;
            Bs[lk + 3][row] = bv.w;
        }
        __syncthreads();

#pragma unroll
        for (int k = 0; k < 16; k++) {
            float4 a0 = *(const float4*)&As[k][ty * 8];
            float4 a1 = *(const float4*)&As[k][ty * 8 + 4];
            float4 b0 = *(const float4*)&Bs[k][tx * 8];
            float4 b1 = *(const float4*)&Bs[k][tx * 8 + 4];
            float af[8] = {a0.x, a0.y, a0.z, a0.w, a1.x, a1.y, a1.z, a1.w};
            float bf[8] = {b0.x, b0.y, b0.z, b0.w, b1.x, b1.y, b1.z, b1.w};
#pragma unroll
            for (int i = 0; i < 8; i++)
#pragma unroll
                for (int j = 0; j < 8; j++) acc[i][j] += af[i] * bf[j];
        }
        __syncthreads();
    }

#pragma unroll
    for (int i = 0; i < 8; i++) {
        float* Crow = C + (size_t)(m0 + ty * 8 + i) * N + n0 + tx * 8;
        float4 c0 = {acc[i][0], acc[i][1], acc[i][2], acc[i][3]};
        float4 c1 = {acc[i][4], acc[i][5], acc[i][6], acc[i][7]};
        *(float4*)(Crow)     = c0;
        *(float4*)(Crow + 4) = c1;
    }
}

// ---------------------------------------------------------------------------
// Flash attention, fp32, online softmax.
// Grid: (S/64, B*NH). 256 threads. One CTA = 64 query rows over all 2048 keys
// in 64-key tiles. Q/K/V are [B,S,D] with the head at column offset h*HD
// (row stride D). Output written to Y in [B,S,D] layout.
//
// Dynamic smem layout (floats), stride 68 keeps float4 alignment (68%4==0):
//   Qs [hd][q]   64x68   (transposed: inner product over hd reads float4 rows)
//   Ks [hd][kk]  64x68
//   Vs [kk][hd]  64x68   (natural)
//   Ps [kk][q]   64x68   (transposed scores/probs)
//   mrow/lrow/crow [64] each
// ---------------------------------------------------------------------------
#define ATTN_SMEM_FLOATS (4 * 64 * 68 + 3 * 64)
#define ATTN_SMEM_BYTES  (ATTN_SMEM_FLOATS * 4)

__global__ void __launch_bounds__(256) attn_kernel(const float* __restrict__ Q,
                                                   const float* __restrict__ K,
                                                   const float* __restrict__ V,
                                                   float* __restrict__ Y)
{
    extern __shared__ float sm[];
    float* Qs   = sm;
    float* Ks   = sm + 64 * 68;
    float* Vs   = sm + 2 * 64 * 68;
    float* Ps   = sm + 3 * 64 * 68;
    float* mrow = sm + 4 * 64 * 68;
    float* lrow = mrow + 64;
    float* crow = lrow + 64;

    const int tid = threadIdx.x;
    const int tx  = tid & 15;
    const int ty  = tid >> 4;
    const int r0  = ty * 4;    // query rows of this thread's microtile
    const int c0  = tx * 4;    // cols (kk in phase1, hd in phase3)

    const int bh = blockIdx.y;
    const int b  = bh >> 4;    // NH = 16
    const int h  = bh & 15;
    const int q0 = blockIdx.x * 64;

    const size_t base = (size_t)b * SS * DD + (size_t)h * HD;
    const float* Qp = Q + base;
    const float* Kp = K + base;
    const float* Vp = V + base;
    const float scale = 0.125f;  // 1/sqrt(64)

    // Load Q tile transposed: Qs[hd][q]
#pragma unroll 4
    for (int i = tid; i < 4096; i += 256) {
        const int q  = i >> 6;
        const int hd = i & 63;
        Qs[hd * 68 + q] = Qp[(size_t)(q0 + q) * DD + hd];
    }
    if (tid < 64) { mrow[tid] = -1e30f; lrow[tid] = 0.f; }

    float acc[4][4];
#pragma unroll
    for (int i = 0; i < 4; i++)
#pragma unroll
        for (int j = 0; j < 4; j++) acc[i][j] = 0.f;

    __syncthreads();

    for (int kt = 0; kt < 32; kt++) {
        const int kk0 = kt * 64;

        // Load K (transposed) and V (natural) tiles
#pragma unroll 4
        for (int i = tid; i < 4096; i += 256) {
            const int kk = i >> 6;
            const int hd = i & 63;
            const size_t g = (size_t)(kk0 + kk) * DD + hd;
            Ks[hd * 68 + kk] = Kp[g];
            Vs[kk * 68 + hd] = Vp[g];
        }
        __syncthreads();

        // Phase 1: S = Q K^T (microtile 4x4), store scaled into Ps[kk][q]
        {
            float s[4][4];
#pragma unroll
            for (int i = 0; i < 4; i++)
#pragma unroll
                for (int j = 0; j < 4; j++) s[i][j] = 0.f;

#pragma unroll 8
            for (int hd = 0; hd < 64; hd++) {
                float4 aq = *(const float4*)&Qs[hd * 68 + r0];
                float4 bk = *(const float4*)&Ks[hd * 68 + c0];
                float af[4] = {aq.x, aq.y, aq.z, aq.w};
                float bf[4] = {bk.x, bk.y, bk.z, bk.w};
#pragma unroll
                for (int i = 0; i < 4; i++)
#pragma unroll
                    for (int j = 0; j < 4; j++) s[i][j] += af[i] * bf[j];
            }
#pragma unroll
            for (int j = 0; j < 4; j++)
#pragma unroll
                for (int i = 0; i < 4; i++)
                    Ps[(c0 + j) * 68 + (r0 + i)] = s[i][j] * scale;
        }
        __syncthreads();

        // Phase 2: online softmax. 4 threads per query row, 16 cols each.
        {
            const int q = tid >> 2;
            const int g = tid & 3;
            float vals[16];
            float mloc = -1e30f;
#pragma unroll
            for (int j = 0; j < 16; j++) {
                vals[j] = Ps[(g * 16 + j) * 68 + q];
                mloc = fmaxf(mloc, vals[j]);
            }
            mloc = fmaxf(mloc, __shfl_xor_sync(0xffffffffu, mloc, 1));
            mloc = fmaxf(mloc, __shfl_xor_sync(0xffffffffu, mloc, 2));
            const float mold = mrow[q];
            const float mnew = fmaxf(mold, mloc);
            float ssum = 0.f;
#pragma unroll
            for (int j = 0; j < 16; j++) {
                float p = __expf(vals[j] - mnew);
                Ps[(g * 16 + j) * 68 + q] = p;
                ssum += p;
            }
            ssum += __shfl_xor_sync(0xffffffffu, ssum, 1);
            ssum += __shfl_xor_sync(0xffffffffu, ssum, 2);
            if (g == 0) {
                const float cf = __expf(mold - mnew);
                crow[q] = cf;
                lrow[q] = lrow[q] * cf + ssum;
                mrow[q] = mnew;
            }
        }
        __syncthreads();

        // Phase 3: rescale accumulator, then O += P V
        {
            float cf[4];
#pragma unroll
            for (int i = 0; i < 4; i++) cf[i] = crow[r0 + i];
#pragma unroll
            for (int i = 0; i < 4; i++)
#pragma unroll
                for (int j = 0; j < 4; j++) acc[i][j] *= cf[i];

#pragma unroll 8
            for (int kk = 0; kk < 64; kk++) {
                const float p0 = Ps[kk * 68 + r0 + 0];
                const float p1 = Ps[kk * 68 + r0 + 1];
                const float p2 = Ps[kk * 68 + r0 + 2];
                const float p3 = Ps[kk * 68 + r0 + 3];
                float4 v = *(const float4*)&Vs[kk * 68 + c0];
                float vf[4] = {v.x, v.y, v.z, v.w};
#pragma unroll
                for (int j = 0; j < 4; j++) {
                    acc[0][j] += p0 * vf[j];
                    acc[1][j] += p1 * vf[j];
                    acc[2][j] += p2 * vf[j];
                    acc[3][j] += p3 * vf[j];
                }
            }
        }
        __syncthreads();
    }

    // Normalize and write out: Y[b][q0+r][h*64 + c]
#pragma unroll
    for (int i = 0; i < 4; i++) {
        const float li = 1.f / lrow[r0 + i];
        float4 o = {acc[i][0] * li, acc[i][1] * li, acc[i][2] * li, acc[i][3] * li};
        *(float4*)&Y[(size_t)(b * SS + q0 + r0 + i) * DD + h * HD + c0] = o;
    }
}

// ---------------------------------------------------------------------------
// Launch
// ---------------------------------------------------------------------------
extern "C" void kernel_launch(void* const* d_in, const int* in_sizes, int n_in,
                              void* d_out, int out_size)
{
    const float* x  = (const float*)d_in[0];
    const float* Wq = (const float*)d_in[1];
    const float* Wk = (const float*)d_in[2];
    const float* Wv = (const float*)d_in[3];
    const float* Wo = (const float*)d_in[4];
    float* out = (float*)d_out;

    float *qp, *kp, *vp, *yp;
    cudaGetSymbolAddress((void**)&qp, g_q);
    cudaGetSymbolAddress((void**)&kp, g_k);
    cudaGetSymbolAddress((void**)&vp, g_v);
    cudaGetSymbolAddress((void**)&yp, g_y);

    cudaFuncSetAttribute(attn_kernel, cudaFuncAttributeMaxDynamicSharedMemorySize,
                         ATTN_SMEM_BYTES);

    const int M = BB * SS;   // 8192
    const int N = DD;        // 1024
    const int K = DD;        // 1024
    dim3 gthreads(256);
    dim3 ggrid(N / 128, M / 128);  // (8, 64)

    sgemm_nt<<<ggrid, gthreads>>>(x, Wq, qp, M, N, K);
    sgemm_nt<<<ggrid, gthreads>>>(x, Wk, kp, M, N, K);
    sgemm_nt<<<ggrid, gthreads>>>(x, Wv, vp, M, N, K);

    dim3 agrid(SS / 64, BB * NH);  // (32, 64)
    attn_kernel<<<agrid, 256, ATTN_SMEM_BYTES>>>(qp, kp, vp, yp);

    sgemm_nt<<<ggrid, gthreads>>>(yp, Wo, out, M, N, K);
}

// round 2
// speedup vs baseline: 2.9818x; 2.9818x over previous
#include <cuda_runtime.h>
#include <cuda_bf16.h>
#include <stdint.h>

#define BB 4
#define SS 2048
#define DDIM 1024
#define NHEAD 16
#define HDIM 64
#define MTOT (BB*SS)   // 8192

// ---------------------------------------------------------------------------
// Scratch (device globals; no allocations allowed)
// ---------------------------------------------------------------------------
__device__ __nv_bfloat16 g_xhi[MTOT*DDIM], g_xlo[MTOT*DDIM];
__device__ __nv_bfloat16 g_wqhi[DDIM*DDIM], g_wqlo[DDIM*DDIM];
__device__ __nv_bfloat16 g_wkhi[DDIM*DDIM], g_wklo[DDIM*DDIM];
__device__ __nv_bfloat16 g_wvhi[DDIM*DDIM], g_wvlo[DDIM*DDIM];
__device__ __nv_bfloat16 g_wohi[DDIM*DDIM], g_wolo[DDIM*DDIM];
__device__ __nv_bfloat16 g_qhi[MTOT*DDIM], g_qlo[MTOT*DDIM];
__device__ __nv_bfloat16 g_khi[MTOT*DDIM], g_klo[MTOT*DDIM];
__device__ __nv_bfloat16 g_vhi[MTOT*DDIM], g_vlo[MTOT*DDIM];
__device__ __nv_bfloat16 g_yhi[MTOT*DDIM], g_ylo[MTOT*DDIM];

// ---------------------------------------------------------------------------
// PTX helpers
// ---------------------------------------------------------------------------
__device__ __forceinline__ uint32_t smem_u32(const void* p) {
    return (uint32_t)__cvta_generic_to_shared(p);
}
__device__ __forceinline__ void cp16(void* s, const void* g) {
    asm volatile("cp.async.cg.shared.global [%0], [%1], 16;\n"
                 :: "r"(smem_u32(s)), "l"(g));
}
__device__ __forceinline__ void cp_commit() { asm volatile("cp.async.commit_group;\n"); }
template<int N> __device__ __forceinline__ void cp_wait() {
    asm volatile("cp.async.wait_group %0;\n" :: "n"(N));
}
__device__ __forceinline__ void ldm_x4(uint32_t& r0, uint32_t& r1, uint32_t& r2, uint32_t& r3,
                                       uint32_t a) {
    asm volatile("ldmatrix.sync.aligned.m8n8.x4.shared.b16 {%0,%1,%2,%3}, [%4];\n"
                 : "=r"(r0), "=r"(r1), "=r"(r2), "=r"(r3) : "r"(a));
}
__device__ __forceinline__ void ldm_x4t(uint32_t& r0, uint32_t& r1, uint32_t& r2, uint32_t& r3,
                                        uint32_t a) {
    asm volatile("ldmatrix.sync.aligned.m8n8.x4.trans.shared.b16 {%0,%1,%2,%3}, [%4];\n"
                 : "=r"(r0), "=r"(r1), "=r"(r2), "=r"(r3) : "r"(a));
}
__device__ __forceinline__ void mma16816(float* c, const uint32_t* a, const uint32_t* b) {
    asm volatile("mma.sync.aligned.m16n8k16.row.col.f32.bf16.bf16.f32 "
                 "{%0,%1,%2,%3}, {%4,%5,%6,%7}, {%8,%9}, {%0,%1,%2,%3};\n"
                 : "+f"(c[0]), "+f"(c[1]), "+f"(c[2]), "+f"(c[3])
                 : "r"(a[0]), "r"(a[1]), "r"(a[2]), "r"(a[3]), "r"(b[0]), "r"(b[1]));
}
// split (x,y) pair into hi/lo bf16x2 packed words
__device__ __forceinline__ void split2(float x, float y, uint32_t& h, uint32_t& l) {
    __nv_bfloat16 hx = __float2bfloat16(x), hy = __float2bfloat16(y);
    __nv_bfloat162 hv; hv.x = hx; hv.y = hy;
    __nv_bfloat162 lv = __floats2bfloat162_rn(x - __bfloat162float(hx),
                                              y - __bfloat162float(hy));
    h = *reinterpret_cast<uint32_t*>(&hv);
    l = *reinterpret_cast<uint32_t*>(&lv);
}

// ---------------------------------------------------------------------------
// fp32 -> (hi,lo) bf16 split
// ---------------------------------------------------------------------------
__global__ void split_kernel(const float4* __restrict__ src,
                             __nv_bfloat162* __restrict__ hi,
                             __nv_bfloat162* __restrict__ lo, int n4) {
    int i = blockIdx.x * blockDim.x + threadIdx.x;
    if (i >= n4) return;
    float4 v = src[i];
    uint32_t h0, l0, h1, l1;
    split2(v.x, v.y, h0, l0);
    split2(v.z, v.w, h1, l1);
    hi[2*i]   = *reinterpret_cast<__nv_bfloat162*>(&h0);
    hi[2*i+1] = *reinterpret_cast<__nv_bfloat162*>(&h1);
    lo[2*i]   = *reinterpret_cast<__nv_bfloat162*>(&l0);
    lo[2*i+1] = *reinterpret_cast<__nv_bfloat162*>(&l1);
}

// ---------------------------------------------------------------------------
// bf16x3 GEMM: C[m][n] = sum_k A[m][k]*B[n][k]  (A,B given as hi/lo bf16)
// BM=128, BN=64, BK=32; 256 threads = 8 warps (4m x 2n), warp tile 32x32.
// Double-buffered cp.async; XOR-swizzled smem for conflict-free ldmatrix.
// SPLIT_OUT: write (Chi, Clo) bf16 split instead of fp32 C.
// ---------------------------------------------------------------------------
template<bool SPLIT_OUT>
__global__ void __launch_bounds__(256) gemm_bf16x3(
    const __nv_bfloat16* __restrict__ Ahi, const __nv_bfloat16* __restrict__ Alo,
    const __nv_bfloat16* __restrict__ Bhi, const __nv_bfloat16* __restrict__ Blo,
    float* __restrict__ C,
    __nv_bfloat16* __restrict__ Chi, __nv_bfloat16* __restrict__ Clo,
    int M, int N, int K)
{
    extern __shared__ uint4 gsm[];
    uint4* sA = gsm;          // [stage][hl][512]  : 128 rows x 4 chunks
    uint4* sB = gsm + 2048;   // [stage][hl][256]  : 64 rows x 4 chunks

    const int tid  = threadIdx.x;
    const int lane = tid & 31;
    const int warp = tid >> 5;
    const int wm = warp >> 1, wn = warp & 1;
    const int m0 = blockIdx.y * 128;
    const int n0 = blockIdx.x * 64;

    float acc[2][4][4];
#pragma unroll
    for (int a = 0; a < 2; a++)
#pragma unroll
        for (int b = 0; b < 4; b++)
#pragma unroll
            for (int c = 0; c < 4; c++) acc[a][b][c] = 0.f;

    auto load_stage = [&](int st, int kt) {
        const int k0 = kt * 32;
#pragma unroll
        for (int r = 0; r < 2; r++) {
            int c   = tid + r * 256;
            int row = c >> 2, kc = c & 3;
            int sidx = (row << 2) + (kc ^ (row & 3));
            size_t g = (size_t)(m0 + row) * K + k0 + kc * 8;
            cp16(&sA[(st*2+0)*512 + sidx], Ahi + g);
            cp16(&sA[(st*2+1)*512 + sidx], Alo + g);
        }
        {
            int row = tid >> 2, kc = tid & 3;
            int sidx = (row << 2) + (kc ^ (row & 3));
            size_t g = (size_t)(n0 + row) * K + k0 + kc * 8;
            cp16(&sB[(st*2+0)*256 + sidx], Bhi + g);
            cp16(&sB[(st*2+1)*256 + sidx], Blo + g);
        }
    };

    load_stage(0, 0);
    cp_commit();

    const int NT = K / 32;
    int buf = 0;
    for (int kt = 0; kt < NT; kt++) {
        if (kt + 1 < NT) { load_stage(buf ^ 1, kt + 1); cp_commit(); cp_wait<1>(); }
        else             { cp_wait<0>(); }
        __syncthreads();

#pragma unroll
        for (int kh = 0; kh < 2; kh++) {
            uint32_t ah[2][4], al[2][4], bh[4][2], bl[4][2];
#pragma unroll
            for (int mt = 0; mt < 2; mt++) {
                int row = wm * 32 + mt * 16 + (lane & 15);
                int kc  = (kh * 2 + (lane >> 4)) ^ (row & 3);
                ldm_x4(ah[mt][0], ah[mt][1], ah[mt][2], ah[mt][3],
                       smem_u32(&sA[(buf*2+0)*512 + (row << 2) + kc]));
                ldm_x4(al[mt][0], al[mt][1], al[mt][2], al[mt][3],
                       smem_u32(&sA[(buf*2+1)*512 + (row << 2) + kc]));
            }
#pragma unroll
            for (int ng = 0; ng < 2; ng++) {
                int row = wn * 32 + ng * 16 + (lane & 15);
                int kc  = (kh * 2 + (lane >> 4)) ^ (row & 3);
                uint32_t r0, r1, r2, r3;
                ldm_x4(r0, r1, r2, r3, smem_u32(&sB[(buf*2+0)*256 + (row << 2) + kc]));
                bh[ng*2+0][0] = r0; bh[ng*2+0][1] = r2;
                bh[ng*2+1][0] = r1; bh[ng*2+1][1] = r3;
                ldm_x4(r0, r1, r2, r3, smem_u32(&sB[(buf*2+1)*256 + (row << 2) + kc]));
                bl[ng*2+0][0] = r0; bl[ng*2+0][1] = r2;
                bl[ng*2+1][0] = r1; bl[ng*2+1][1] = r3;
            }
#pragma unroll
            for (int mt = 0; mt < 2; mt++)
#pragma unroll
                for (int nt = 0; nt < 4; nt++) {
                    mma16816(acc[mt][nt], ah[mt], bh[nt]);
                    mma16816(acc[mt][nt], ah[mt], bl[nt]);
                    mma16816(acc[mt][nt], al[mt], bh[nt]);
                }
        }
        __syncthreads();
        buf ^= 1;
    }

    // epilogue
#pragma unroll
    for (int mt = 0; mt < 2; mt++)
#pragma unroll
        for (int nt = 0; nt < 4; nt++) {
            int r  = m0 + wm * 32 + mt * 16 + (lane >> 2);
            int cc = n0 + wn * 32 + nt * 8 + (lane & 3) * 2;
            if (SPLIT_OUT) {
                uint32_t h0, l0, h1, l1;
                split2(acc[mt][nt][0], acc[mt][nt][1], h0, l0);
                split2(acc[mt][nt][2], acc[mt][nt][3], h1, l1);
                *reinterpret_cast<uint32_t*>(&Chi[(size_t)r * N + cc])       = h0;
                *reinterpret_cast<uint32_t*>(&Clo[(size_t)r * N + cc])       = l0;
                *reinterpret_cast<uint32_t*>(&Chi[(size_t)(r + 8) * N + cc]) = h1;
                *reinterpret_cast<uint32_t*>(&Clo[(size_t)(r + 8) * N + cc]) = l1;
            } else {
                float2 v0 = {acc[mt][nt][0], acc[mt][nt][1]};
                float2 v1 = {acc[mt][nt][2], acc[mt][nt][3]};
                *reinterpret_cast<float2*>(&C[(size_t)r * N + cc])       = v0;
                *reinterpret_cast<float2*>(&C[(size_t)(r + 8) * N + cc]) = v1;
            }
        }
}

// ---------------------------------------------------------------------------
// Flash attention, bf16x3 tensor-core version.
// Grid: (S/64, B*NH). 128 threads = 4 warps; each warp owns 16 full query
// rows -> softmax is warp-local (shfl only). Q frags cached in registers.
// K/V tiles double-buffered via cp.async. P stays in registers (C-frag
// layout == A-frag layout), split hi/lo on the fly for the PV MMAs.
// ---------------------------------------------------------------------------
__global__ void __launch_bounds__(128) attn_bf16x3(
    const __nv_bfloat16* __restrict__ Qhi, const __nv_bfloat16* __restrict__ Qlo,
    const __nv_bfloat16* __restrict__ Khi, const __nv_bfloat16* __restrict__ Klo,
    const __nv_bfloat16* __restrict__ Vhi, const __nv_bfloat16* __restrict__ Vlo,
    __nv_bfloat16* __restrict__ Yhi, __nv_bfloat16* __restrict__ Ylo)
{
    extern __shared__ uint4 smem[];
    uint4* sQ = smem;          // [hl][512]        : 64 rows x 8 chunks
    uint4* sK = smem + 1024;   // [stage][hl][512]
    uint4* sV = smem + 3072;   // [stage][hl][512]

    const int tid = threadIdx.x, lane = tid & 31, warp = tid >> 5;
    const int bh = blockIdx.y, b = bh >> 4, h = bh & 15;
    const int q0 = blockIdx.x * 64;
    const size_t base = (size_t)b * SS * DDIM + h * HDIM;

    auto load_kv = [&](int st, int kt) {
        const int kk0 = kt * 64;
#pragma unroll
        for (int r = 0; r < 4; r++) {
            int c = tid + r * 128;
            int row = c >> 3, hc = c & 7;
            int sidx = (row << 3) + (hc ^ (row & 7));
            size_t g = base + (size_t)(kk0 + row) * DDIM + hc * 8;
            cp16(&sK[(st*2+0)*512 + sidx], Khi + g);
            cp16(&sK[(st*2+1)*512 + sidx], Klo + g);
            cp16(&sV[(st*2+0)*512 + sidx], Vhi + g);
            cp16(&sV[(st*2+1)*512 + sidx], Vlo + g);
        }
    };

    // Q tile + stage-0 K/V in one group
#pragma unroll
    for (int r = 0; r < 4; r++) {
        int c = tid + r * 128;
        int row = c >> 3, hc = c & 7;
        int sidx = (row << 3) + (hc ^ (row & 7));
        size_t g = base + (size_t)(q0 + row) * DDIM + hc * 8;
        cp16(&sQ[sidx],       Qhi + g);
        cp16(&sQ[512 + sidx], Qlo + g);
    }
    load_kv(0, 0);
    cp_commit();

    uint32_t qh[4][4], ql[4][4];
    float o[8][4];
#pragma unroll
    for (int i = 0; i < 8; i++)
#pragma unroll
        for (int j = 0; j < 4; j++) o[i][j] = 0.f;
    float m0r = -1e30f, m1r = -1e30f, l0r = 0.f, l1r = 0.f;

    int buf = 0;
    for (int kt = 0; kt < 32; kt++) {
        if (kt < 31) { load_kv(buf ^ 1, kt + 1); cp_commit(); cp_wait<1>(); }
        else         { cp_wait<0>(); }
        __syncthreads();

        if (kt == 0) {
#pragma unroll
            for (int kc = 0; kc < 4; kc++) {
                int row = warp * 16 + (lane & 15);
                int hc  = (kc * 2 + (lane >> 4)) ^ (row & 7);
                ldm_x4(qh[kc][0], qh[kc][1], qh[kc][2], qh[kc][3],
                       smem_u32(&sQ[(row << 3) + hc]));
                ldm_x4(ql[kc][0], ql[kc][1], ql[kc][2], ql[kc][3],
                       smem_u32(&sQ[512 + (row << 3) + hc]));
            }
        }

        // ---- S = Q K^T ----
        float s[8][4];
#pragma unroll
        for (int i = 0; i < 8; i++)
#pragma unroll
            for (int j = 0; j < 4; j++) s[i][j] = 0.f;

#pragma unroll
        for (int kc = 0; kc < 4; kc++) {
            uint32_t bhf[8][2], blf[8][2];
#pragma unroll
            for (int ng = 0; ng < 4; ng++) {
                int row = ng * 16 + (lane & 15);
                int hc  = (kc * 2 + (lane >> 4)) ^ (row & 7);
                uint32_t r0, r1, r2, r3;
                ldm_x4(r0, r1, r2, r3, smem_u32(&sK[(buf*2+0)*512 + (row << 3) + hc]));
                bhf[ng*2+0][0] = r0; bhf[ng*2+0][1] = r2;
                bhf[ng*2+1][0] = r1; bhf[ng*2+1][1] = r3;
                ldm_x4(r0, r1, r2, r3, smem_u32(&sK[(buf*2+1)*512 + (row << 3) + hc]));
                blf[ng*2+0][0] = r0; blf[ng*2+0][1] = r2;
                blf[ng*2+1][0] = r1; blf[ng*2+1][1] = r3;
            }
#pragma unroll
            for (int nt = 0; nt < 8; nt++) {
                mma16816(s[nt], qh[kc], bhf[nt]);
                mma16816(s[nt], qh[kc], blf[nt]);
                mma16816(s[nt], ql[kc], bhf[nt]);
            }
        }

        // ---- online softmax (warp-local) ----
        float mn0 = -1e30f, mn1 = -1e30f;
#pragma unroll
        for (int nt = 0; nt < 8; nt++) {
            s[nt][0] *= 0.125f; s[nt][1] *= 0.125f;
            s[nt][2] *= 0.125f; s[nt][3] *= 0.125f;
            mn0 = fmaxf(mn0, fmaxf(s[nt][0], s[nt][1]));
            mn1 = fmaxf(mn1, fmaxf(s[nt][2], s[nt][3]));
        }
        mn0 = fmaxf(mn0, __shfl_xor_sync(0xffffffffu, mn0, 1));
        mn0 = fmaxf(mn0, __shfl_xor_sync(0xffffffffu, mn0, 2));
        mn1 = fmaxf(mn1, __shfl_xor_sync(0xffffffffu, mn1, 1));
        mn1 = fmaxf(mn1, __shfl_xor_sync(0xffffffffu, mn1, 2));
        float mnew0 = fmaxf(m0r, mn0), mnew1 = fmaxf(m1r, mn1);
        float cf0 = __expf(m0r - mnew0), cf1 = __expf(m1r - mnew1);
        m0r = mnew0; m1r = mnew1;
        float ps0 = 0.f, ps1 = 0.f;
#pragma unroll
        for (int nt = 0; nt < 8; nt++) {
            s[nt][0] = __expf(s[nt][0] - mnew0);
            s[nt][1] = __expf(s[nt][1] - mnew0);
            s[nt][2] = __expf(s[nt][2] - mnew1);
            s[nt][3] = __expf(s[nt][3] - mnew1);
            ps0 += s[nt][0] + s[nt][1];
            ps1 += s[nt][2] + s[nt][3];
        }
        ps0 += __shfl_xor_sync(0xffffffffu, ps0, 1);
        ps0 += __shfl_xor_sync(0xffffffffu, ps0, 2);
        ps1 += __shfl_xor_sync(0xffffffffu, ps1, 1);
        ps1 += __shfl_xor_sync(0xffffffffu, ps1, 2);
        l0r = l0r * cf0 + ps0;
        l1r = l1r * cf1 + ps1;
#pragma unroll
        for (int nt = 0; nt < 8; nt++) {
            o[nt][0] *= cf0; o[nt][1] *= cf0;
            o[nt][2] *= cf1; o[nt][3] *= cf1;
        }

        // ---- O += P V ----
#pragma unroll
        for (int kc = 0; kc < 4; kc++) {
            uint32_t ph[4], pl[4];
            split2(s[2*kc][0],   s[2*kc][1],   ph[0], pl[0]);
            split2(s[2*kc][2],   s[2*kc][3],   ph[1], pl[1]);
            split2(s[2*kc+1][0], s[2*kc+1][1], ph[2], pl[2]);
            split2(s[2*kc+1][2], s[2*kc+1][3], ph[3], pl[3]);
            uint32_t vh[8][2], vl[8][2];
#pragma unroll
            for (int np = 0; np < 4; np++) {
                int row = kc * 16 + (lane & 15);
                int hc  = (np * 2 + (lane >> 4)) ^ (row & 7);
                uint32_t r0, r1, r2, r3;
                ldm_x4t(r0, r1, r2, r3, smem_u32(&sV[(buf*2+0)*512 + (row << 3) + hc]));
                vh[np*2+0][0] = r0; vh[np*2+0][1] = r1;
                vh[np*2+1][0] = r2; vh[np*2+1][1] = r3;
                ldm_x4t(r0, r1, r2, r3, smem_u32(&sV[(buf*2+1)*512 + (row << 3) + hc]));
                vl[np*2+0][0] = r0; vl[np*2+0][1] = r1;
                vl[np*2+1][0] = r2; vl[np*2+1][1] = r3;
            }
#pragma unroll
            for (int nt = 0; nt < 8; nt++) {
                mma16816(o[nt], ph, vh[nt]);
                mma16816(o[nt], ph, vl[nt]);
                mma16816(o[nt], pl, vh[nt]);
            }
        }
        __syncthreads();
        buf ^= 1;
    }

    // ---- normalize + split-write y ----
    float inv0 = 1.f / l0r, inv1 = 1.f / l1r;
    int r = q0 + warp * 16 + (lane >> 2);
#pragma unroll
    for (int nt = 0; nt < 8; nt++) {
        int c = nt * 8 + (lane & 3) * 2;
        uint32_t hA, lA, hB, lB;
        split2(o[nt][0] * inv0, o[nt][1] * inv0, hA, lA);
        split2(o[nt][2] * inv1, o[nt][3] * inv1, hB, lB);
        size_t gA = (size_t)b * SS * DDIM + (size_t)r * DDIM + h * HDIM + c;
        size_t gB = gA + (size_t)8 * DDIM;
        *reinterpret_cast<uint32_t*>(&Yhi[gA]) = hA;
        *reinterpret_cast<uint32_t*>(&Ylo[gA]) = lA;
        *reinterpret_cast<uint32_t*>(&Yhi[gB]) = hB;
        *reinterpret_cast<uint32_t*>(&Ylo[gB]) = lB;
    }
}

// ---------------------------------------------------------------------------
// Launch
// ---------------------------------------------------------------------------
extern "C" void kernel_launch(void* const* d_in, const int* in_sizes, int n_in,
                              void* d_out, int out_size)
{
    const float* x  = (const float*)d_in[0];
    const float* Wq = (const float*)d_in[1];
    const float* Wk = (const float*)d_in[2];
    const float* Wv = (const float*)d_in[3];
    const float* Wo = (const float*)d_in[4];
    float* out = (float*)d_out;

    __nv_bfloat16 *xhi, *xlo, *wqhi, *wqlo, *wkhi, *wklo, *wvhi, *wvlo, *wohi, *wolo;
    __nv_bfloat16 *qhi, *qlo, *khi, *klo, *vhi, *vlo, *yhi, *ylo;
    cudaGetSymbolAddress((void**)&xhi, g_xhi);   cudaGetSymbolAddress((void**)&xlo, g_xlo);
    cudaGetSymbolAddress((void**)&wqhi, g_wqhi); cudaGetSymbolAddress((void**)&wqlo, g_wqlo);
    cudaGetSymbolAddress((void**)&wkhi, g_wkhi); cudaGetSymbolAddress((void**)&wklo, g_wklo);
    cudaGetSymbolAddress((void**)&wvhi, g_wvhi); cudaGetSymbolAddress((void**)&wvlo, g_wvlo);
    cudaGetSymbolAddress((void**)&wohi, g_wohi); cudaGetSymbolAddress((void**)&wolo, g_wolo);
    cudaGetSymbolAddress((void**)&qhi, g_qhi);   cudaGetSymbolAddress((void**)&qlo, g_qlo);
    cudaGetSymbolAddress((void**)&khi, g_khi);   cudaGetSymbolAddress((void**)&klo, g_klo);
    cudaGetSymbolAddress((void**)&vhi, g_vhi);   cudaGetSymbolAddress((void**)&vlo, g_vlo);
    cudaGetSymbolAddress((void**)&yhi, g_yhi);   cudaGetSymbolAddress((void**)&ylo, g_ylo);

    cudaFuncSetAttribute(gemm_bf16x3<true>,  cudaFuncAttributeMaxDynamicSharedMemorySize, 49152);
    cudaFuncSetAttribute(gemm_bf16x3<false>, cudaFuncAttributeMaxDynamicSharedMemorySize, 49152);
    cudaFuncSetAttribute(attn_bf16x3, cudaFuncAttributeMaxDynamicSharedMemorySize, 81920);

    // splits
    {
        int n4 = MTOT * DDIM / 4;
        split_kernel<<<(n4 + 255) / 256, 256>>>((const float4*)x,
                                                (__nv_bfloat162*)xhi, (__nv_bfloat162*)xlo, n4);
        int w4 = DDIM * DDIM / 4;
        split_kernel<<<(w4 + 255) / 256, 256>>>((const float4*)Wq,
                                                (__nv_bfloat162*)wqhi, (__nv_bfloat162*)wqlo, w4);
        split_kernel<<<(w4 + 255) / 256, 256>>>((const float4*)Wk,
                                                (__nv_bfloat162*)wkhi, (__nv_bfloat162*)wklo, w4);
        split_kernel<<<(w4 + 255) / 256, 256>>>((const float4*)Wv,
                                                (__nv_bfloat162*)wvhi, (__nv_bfloat162*)wvlo, w4);
        split_kernel<<<(w4 + 255) / 256, 256>>>((const float4*)Wo,
                                                (__nv_bfloat162*)wohi, (__nv_bfloat162*)wolo, w4);
    }

    dim3 gg(DDIM / 64, MTOT / 128);  // (16, 64)
    gemm_bf16x3<true><<<gg, 256, 49152>>>(xhi, xlo, wqhi, wqlo,
                                          nullptr, qhi, qlo, MTOT, DDIM, DDIM);
    gemm_bf16x3<true><<<gg, 256, 49152>>>(xhi, xlo, wkhi, wklo,
                                          nullptr, khi, klo, MTOT, DDIM, DDIM);
    gemm_bf16x3<true><<<gg, 256, 49152>>>(xhi, xlo, wvhi, wvlo,
                                          nullptr, vhi, vlo, MTOT, DDIM, DDIM);

    dim3 ag(SS / 64, BB * NHEAD);  // (32, 64)
    attn_bf16x3<<<ag, 128, 81920>>>(qhi, qlo, khi, klo, vhi, vlo, yhi, ylo);

    gemm_bf16x3<false><<<gg, 256, 49152>>>(yhi, ylo, wohi, wolo,
                                           out, nullptr, nullptr, MTOT, DDIM, DDIM);
}

// round 4
// speedup vs baseline: 3.0241x; 1.0142x over previous
#include <cuda_runtime.h>
#include <cuda_bf16.h>
#include <stdint.h>

#define BB 4
#define SS 2048
#define DDIM 1024
#define NHEAD 16
#define HDIM 64
#define MTOT (BB*SS)   // 8192

// ---------------------------------------------------------------------------
// Scratch (device globals; no allocations allowed)
// ---------------------------------------------------------------------------
__device__ __nv_bfloat16 g_xhi[MTOT*DDIM], g_xlo[MTOT*DDIM];
__device__ __nv_bfloat16 g_wqhi[DDIM*DDIM], g_wqlo[DDIM*DDIM];
__device__ __nv_bfloat16 g_wkhi[DDIM*DDIM], g_wklo[DDIM*DDIM];
__device__ __nv_bfloat16 g_wvhi[DDIM*DDIM], g_wvlo[DDIM*DDIM];
__device__ __nv_bfloat16 g_wohi[DDIM*DDIM], g_wolo[DDIM*DDIM];
__device__ __nv_bfloat16 g_qhi[MTOT*DDIM], g_qlo[MTOT*DDIM];
__device__ __nv_bfloat16 g_khi[MTOT*DDIM], g_klo[MTOT*DDIM];
__device__ __nv_bfloat16 g_vhi[MTOT*DDIM], g_vlo[MTOT*DDIM];
__device__ __nv_bfloat16 g_yhi[MTOT*DDIM], g_ylo[MTOT*DDIM];

// ---------------------------------------------------------------------------
// PTX helpers
// ---------------------------------------------------------------------------
__device__ __forceinline__ uint32_t smem_u32(const void* p) {
    return (uint32_t)__cvta_generic_to_shared(p);
}
__device__ __forceinline__ void cp16(void* s, const void* g) {
    asm volatile("cp.async.cg.shared.global [%0], [%1], 16;\n"
                 :: "r"(smem_u32(s)), "l"(g));
}
__device__ __forceinline__ void cp_commit() { asm volatile("cp.async.commit_group;\n"); }
template<int N> __device__ __forceinline__ void cp_wait() {
    asm volatile("cp.async.wait_group %0;\n" :: "n"(N));
}
__device__ __forceinline__ void ldm_x4(uint32_t& r0, uint32_t& r1, uint32_t& r2, uint32_t& r3,
                                       uint32_t a) {
    asm volatile("ldmatrix.sync.aligned.m8n8.x4.shared.b16 {%0,%1,%2,%3}, [%4];\n"
                 : "=r"(r0), "=r"(r1), "=r"(r2), "=r"(r3) : "r"(a));
}
__device__ __forceinline__ void ldm_x4t(uint32_t& r0, uint32_t& r1, uint32_t& r2, uint32_t& r3,
                                        uint32_t a) {
    asm volatile("ldmatrix.sync.aligned.m8n8.x4.trans.shared.b16 {%0,%1,%2,%3}, [%4];\n"
                 : "=r"(r0), "=r"(r1), "=r"(r2), "=r"(r3) : "r"(a));
}
__device__ __forceinline__ void mma16816(float* c, const uint32_t* a, const uint32_t* b) {
    asm volatile("mma.sync.aligned.m16n8k16.row.col.f32.bf16.bf16.f32 "
                 "{%0,%1,%2,%3}, {%4,%5,%6,%7}, {%8,%9}, {%0,%1,%2,%3};\n"
                 : "+f"(c[0]), "+f"(c[1]), "+f"(c[2]), "+f"(c[3])
                 : "r"(a[0]), "r"(a[1]), "r"(a[2]), "r"(a[3]), "r"(b[0]), "r"(b[1]));
}
__device__ __forceinline__ void split2(float x, float y, uint32_t& h, uint32_t& l) {
    __nv_bfloat16 hx = __float2bfloat16(x), hy = __float2bfloat16(y);
    __nv_bfloat162 hv; hv.x = hx; hv.y = hy;
    __nv_bfloat162 lv = __floats2bfloat162_rn(x - __bfloat162float(hx),
                                              y - __bfloat162float(hy));
    h = *reinterpret_cast<uint32_t*>(&hv);
    l = *reinterpret_cast<uint32_t*>(&lv);
}

// ---------------------------------------------------------------------------
// fp32 -> (hi,lo) bf16 split
// ---------------------------------------------------------------------------
__global__ void split_kernel(const float4* __restrict__ src,
                             __nv_bfloat162* __restrict__ hi,
                             __nv_bfloat162* __restrict__ lo, int n4) {
    int i = blockIdx.x * blockDim.x + threadIdx.x;
    if (i >= n4) return;
    float4 v = src[i];
    uint32_t h0, l0, h1, l1;
    split2(v.x, v.y, h0, l0);
    split2(v.z, v.w, h1, l1);
    hi[2*i]   = *reinterpret_cast<__nv_bfloat162*>(&h0);
    hi[2*i+1] = *reinterpret_cast<__nv_bfloat162*>(&h1);
    lo[2*i]   = *reinterpret_cast<__nv_bfloat162*>(&l0);
    lo[2*i+1] = *reinterpret_cast<__nv_bfloat162*>(&l1);
}

// ---------------------------------------------------------------------------
// bf16x3 GEMM: C[m][n] = sum_k A[m][k]*B[n][k]  (A,B given as hi/lo bf16)
// BM=128, BN=64, BK=32; 256 threads = 8 warps (4m x 2n), warp tile 32x32.
// THREE-stage cp.async pipeline; XOR-swizzled smem for conflict-free ldmatrix.
// Stage layout (uint4 units): sA[st][hl][512], sB[st][hl][256].
// ---------------------------------------------------------------------------
#define G_STAGES 3
#define G_SMEM_U4 (G_STAGES*2*512 + G_STAGES*2*256)   // 4608 uint4 = 72KB
#define G_SMEM_BYTES (G_SMEM_U4*16)

template<bool SPLIT_OUT>
__global__ void __launch_bounds__(256) gemm_bf16x3(
    const __nv_bfloat16* __restrict__ Ahi, const __nv_bfloat16* __restrict__ Alo,
    const __nv_bfloat16* __restrict__ Bhi, const __nv_bfloat16* __restrict__ Blo,
    float* __restrict__ C,
    __nv_bfloat16* __restrict__ Chi, __nv_bfloat16* __restrict__ Clo,
    int M, int N, int K)
{
    extern __shared__ uint4 gsm[];
    uint4* sA = gsm;                       // [3][2][512]
    uint4* sB = gsm + G_STAGES * 2 * 512;  // [3][2][256]

    const int tid  = threadIdx.x;
    const int lane = tid & 31;
    const int warp = tid >> 5;
    const int wm = warp >> 1, wn = warp & 1;
    const int m0 = blockIdx.y * 128;
    const int n0 = blockIdx.x * 64;

    float acc[2][4][4];
#pragma unroll
    for (int a = 0; a < 2; a++)
#pragma unroll
        for (int b = 0; b < 4; b++)
#pragma unroll
            for (int c = 0; c < 4; c++) acc[a][b][c] = 0.f;

    auto load_stage = [&](int st, int kt) {
        const int k0 = kt * 32;
#pragma unroll
        for (int r = 0; r < 2; r++) {
            int c   = tid + r * 256;
            int row = c >> 2, kc = c & 3;
            int sidx = (row << 2) + (kc ^ (row & 3));
            size_t g = (size_t)(m0 + row) * K + k0 + kc * 8;
            cp16(&sA[(st*2+0)*512 + sidx], Ahi + g);
            cp16(&sA[(st*2+1)*512 + sidx], Alo + g);
        }
        {
            int row = tid >> 2, kc = tid & 3;
            int sidx = (row << 2) + (kc ^ (row & 3));
            size_t g = (size_t)(n0 + row) * K + k0 + kc * 8;
            cp16(&sB[(st*2+0)*256 + sidx], Bhi + g);
            cp16(&sB[(st*2+1)*256 + sidx], Blo + g);
        }
    };

    const int NT = K / 32;   // 32
    load_stage(0, 0); cp_commit();
    load_stage(1, 1); cp_commit();

    int st = 0;
    for (int kt = 0; kt < NT; kt++) {
        if (kt + 2 < NT) { load_stage((st + 2) % G_STAGES, kt + 2); cp_commit(); }
        if      (kt + 2 < NT) cp_wait<2>();
        else if (kt + 1 < NT) cp_wait<1>();
        else                  cp_wait<0>();
        __syncthreads();

#pragma unroll
        for (int kh = 0; kh < 2; kh++) {
            uint32_t ah[2][4], al[2][4], bh[4][2], bl[4][2];
#pragma unroll
            for (int mt = 0; mt < 2; mt++) {
                int row = wm * 32 + mt * 16 + (lane & 15);
                int kc  = (kh * 2 + (lane >> 4)) ^ (row & 3);
                ldm_x4(ah[mt][0], ah[mt][1], ah[mt][2], ah[mt][3],
                       smem_u32(&sA[(st*2+0)*512 + (row << 2) + kc]));
                ldm_x4(al[mt][0], al[mt][1], al[mt][2], al[mt][3],
                       smem_u32(&sA[(st*2+1)*512 + (row << 2) + kc]));
            }
#pragma unroll
            for (int ng = 0; ng < 2; ng++) {
                int row = wn * 32 + ng * 16 + (lane & 15);
                int kc  = (kh * 2 + (lane >> 4)) ^ (row & 3);
                uint32_t r0, r1, r2, r3;
                ldm_x4(r0, r1, r2, r3, smem_u32(&sB[(st*2+0)*256 + (row << 2) + kc]));
                bh[ng*2+0][0] = r0; bh[ng*2+0][1] = r2;
                bh[ng*2+1][0] = r1; bh[ng*2+1][1] = r3;
                ldm_x4(r0, r1, r2, r3, smem_u32(&sB[(st*2+1)*256 + (row << 2) + kc]));
                bl[ng*2+0][0] = r0; bl[ng*2+0][1] = r2;
                bl[ng*2+1][0] = r1; bl[ng*2+1][1] = r3;
            }
#pragma unroll
            for (int mt = 0; mt < 2; mt++)
#pragma unroll
                for (int nt = 0; nt < 4; nt++) {
                    mma16816(acc[mt][nt], ah[mt], bh[nt]);
                    mma16816(acc[mt][nt], ah[mt], bl[nt]);
                    mma16816(acc[mt][nt], al[mt], bh[nt]);
                }
        }
        __syncthreads();
        st = (st + 1) % G_STAGES;
    }

    // epilogue
#pragma unroll
    for (int mt = 0; mt < 2; mt++)
#pragma unroll
        for (int nt = 0; nt < 4; nt++) {
            int r  = m0 + wm * 32 + mt * 16 + (lane >> 2);
            int cc = n0 + wn * 32 + nt * 8 + (lane & 3) * 2;
            if (SPLIT_OUT) {
                uint32_t h0, l0, h1, l1;
                split2(acc[mt][nt][0], acc[mt][nt][1], h0, l0);
                split2(acc[mt][nt][2], acc[mt][nt][3], h1, l1);
                *reinterpret_cast<uint32_t*>(&Chi[(size_t)r * N + cc])       = h0;
                *reinterpret_cast<uint32_t*>(&Clo[(size_t)r * N + cc])       = l0;
                *reinterpret_cast<uint32_t*>(&Chi[(size_t)(r + 8) * N + cc]) = h1;
                *reinterpret_cast<uint32_t*>(&Clo[(size_t)(r + 8) * N + cc]) = l1;
            } else {
                float2 v0 = {acc[mt][nt][0], acc[mt][nt][1]};
                float2 v1 = {acc[mt][nt][2], acc[mt][nt][3]};
                *reinterpret_cast<float2*>(&C[(size_t)r * N + cc])       = v0;
                *reinterpret_cast<float2*>(&C[(size_t)(r + 8) * N + cc]) = v1;
            }
        }
}

// ---------------------------------------------------------------------------
// Flash attention, bf16x3 tensor-core version.
// Grid: (S/64, B*NH). 128 threads = 4 warps; each warp owns 16 full query
// rows -> softmax is warp-local. Q frags cached in registers.
// K double-buffered (prefetch next tile); V single-buffered: its load is
// issued at tile top and completes under QK^T + softmax (K/V are L2-hot).
// Smem = 64KB -> 3 CTAs/SM (launch_bounds caps regs at 170).
//
// Smem layout (uint4): sQ[2][512] | sK[2 stages][2][512] | sV[2][512]
// Per-tile cp groups: g(V_kt), g(K_{kt+1}). Waits: before QK leave 2 pending
// (V_kt, K_{kt+1}); before PV leave 1 (K_{kt+1}). Tail adjusts counts.
// ---------------------------------------------------------------------------
#define ATTN_SMEM_BYTES (4096*16)   // 64KB

__global__ void __launch_bounds__(128, 3) attn_bf16x3(
    const __nv_bfloat16* __restrict__ Qhi, const __nv_bfloat16* __restrict__ Qlo,
    const __nv_bfloat16* __restrict__ Khi, const __nv_bfloat16* __restrict__ Klo,
    const __nv_bfloat16* __restrict__ Vhi, const __nv_bfloat16* __restrict__ Vlo,
    __nv_bfloat16* __restrict__ Yhi, __nv_bfloat16* __restrict__ Ylo)
{
    extern __shared__ uint4 smem[];
    uint4* sQ = smem;          // [2][512]
    uint4* sK = smem + 1024;   // [2][2][512]
    uint4* sV = smem + 3072;   // [2][512]

    const int tid = threadIdx.x, lane = tid & 31, warp = tid >> 5;
    const int bh = blockIdx.y, b = bh >> 4, h = bh & 15;
    const int q0 = blockIdx.x * 64;
    const size_t base = (size_t)b * SS * DDIM + h * HDIM;

    auto load_k = [&](int st, int kt) {
        const int kk0 = kt * 64;
#pragma unroll
        for (int r = 0; r < 4; r++) {
            int c = tid + r * 128;
            int row = c >> 3, hc = c & 7;
            int sidx = (row << 3) + (hc ^ (row & 7));
            size_t g = base + (size_t)(kk0 + row) * DDIM + hc * 8;
            cp16(&sK[(st*2+0)*512 + sidx], Khi + g);
            cp16(&sK[(st*2+1)*512 + sidx], Klo + g);
        }
    };
    auto load_v = [&](int kt) {
        const int kk0 = kt * 64;
#pragma unroll
        for (int r = 0; r < 4; r++) {
            int c = tid + r * 128;
            int row = c >> 3, hc = c & 7;
            int sidx = (row << 3) + (hc ^ (row & 7));
            size_t g = base + (size_t)(kk0 + row) * DDIM + hc * 8;
            cp16(&sV[sidx],       Vhi + g);
            cp16(&sV[512 + sidx], Vlo + g);
        }
    };

    // prologue: Q + K(0) in one group
#pragma unroll
    for (int r = 0; r < 4; r++) {
        int c = tid + r * 128;
        int row = c >> 3, hc = c & 7;
        int sidx = (row << 3) + (hc ^ (row & 7));
        size_t g = base + (size_t)(q0 + row) * DDIM + hc * 8;
        cp16(&sQ[sidx],       Qhi + g);
        cp16(&sQ[512 + sidx], Qlo + g);
    }
    load_k(0, 0);
    cp_commit();

    uint32_t qh[4][4], ql[4][4];
    float o[8][4];
#pragma unroll
    for (int i = 0; i < 8; i++)
#pragma unroll
        for (int j = 0; j < 4; j++) o[i][j] = 0.f;
    float m0r = -1e30f, m1r = -1e30f, l0r = 0.f, l1r = 0.f;

    for (int kt = 0; kt < 32; kt++) {
        const int buf = kt & 1;
        // issue this tile's V, next tile's K
        load_v(kt); cp_commit();
        if (kt < 31) { load_k(buf ^ 1, kt + 1); cp_commit(); }
        // wait for K(kt) (and Q at kt=0): leave this tile's issues pending
        if (kt < 31) cp_wait<2>(); else cp_wait<1>();
        __syncthreads();

        if (kt == 0) {
#pragma unroll
            for (int kc = 0; kc < 4; kc++) {
                int row = warp * 16 + (lane & 15);
                int hc  = (kc * 2 + (lane >> 4)) ^ (row & 7);
                ldm_x4(qh[kc][0], qh[kc][1], qh[kc][2], qh[kc][3],
                       smem_u32(&sQ[(row << 3) + hc]));
                ldm_x4(ql[kc][0], ql[kc][1], ql[kc][2], ql[kc][3],
                       smem_u32(&sQ[512 + (row << 3) + hc]));
            }
        }

        // ---- S = Q K^T ----
        float s[8][4];
#pragma unroll
        for (int i = 0; i < 8; i++)
#pragma unroll
            for (int j = 0; j < 4; j++) s[i][j] = 0.f;

#pragma unroll
        for (int kc = 0; kc < 4; kc++) {
            uint32_t bhf[8][2], blf[8][2];
#pragma unroll
            for (int ng = 0; ng < 4; ng++) {
                int row = ng * 16 + (lane & 15);
                int hc  = (kc * 2 + (lane >> 4)) ^ (row & 7);
                uint32_t r0, r1, r2, r3;
                ldm_x4(r0, r1, r2, r3, smem_u32(&sK[(buf*2+0)*512 + (row << 3) + hc]));
                bhf[ng*2+0][0] = r0; bhf[ng*2+0][1] = r2;
                bhf[ng*2+1][0] = r1; bhf[ng*2+1][1] = r3;
                ldm_x4(r0, r1, r2, r3, smem_u32(&sK[(buf*2+1)*512 + (row << 3) + hc]));
                blf[ng*2+0][0] = r0; blf[ng*2+0][1] = r2;
                blf[ng*2+1][0] = r1; blf[ng*2+1][1] = r3;
            }
#pragma unroll
            for (int nt = 0; nt < 8; nt++) {
                mma16816(s[nt], qh[kc], bhf[nt]);
                mma16816(s[nt], qh[kc], blf[nt]);
                mma16816(s[nt], ql[kc], bhf[nt]);
            }
        }

        // ---- online softmax (warp-local) ----
        float mn0 = -1e30f, mn1 = -1e30f;
#pragma unroll
        for (int nt = 0; nt < 8; nt++) {
            s[nt][0] *= 0.125f; s[nt][1] *= 0.125f;
            s[nt][2] *= 0.125f; s[nt][3] *= 0.125f;
            mn0 = fmaxf(mn0, fmaxf(s[nt][0], s[nt][1]));
            mn1 = fmaxf(mn1, fmaxf(s[nt][2], s[nt][3]));
        }
        mn0 = fmaxf(mn0, __shfl_xor_sync(0xffffffffu, mn0, 1));
        mn0 = fmaxf(mn0, __shfl_xor_sync(0xffffffffu, mn0, 2));
        mn1 = fmaxf(mn1, __shfl_xor_sync(0xffffffffu, mn1, 1));
        mn1 = fmaxf(mn1, __shfl_xor_sync(0xffffffffu, mn1, 2));
        float mnew0 = fmaxf(m0r, mn0), mnew1 = fmaxf(m1r, mn1);
        float cf0 = __expf(m0r - mnew0), cf1 = __expf(m1r - mnew1);
        m0r = mnew0; m1r = mnew1;
        float ps0 = 0.f, ps1 = 0.f;
#pragma unroll
        for (int nt = 0; nt < 8; nt++) {
            s[nt][0] = __expf(s[nt][0] - mnew0);
            s[nt][1] = __expf(s[nt][1] - mnew0);
            s[nt][2] = __expf(s[nt][2] - mnew1);
            s[nt][3] = __expf(s[nt][3] - mnew1);
            ps0 += s[nt][0] + s[nt][1];
            ps1 += s[nt][2] + s[nt][3];
        }
        ps0 += __shfl_xor_sync(0xffffffffu, ps0, 1);
        ps0 += __shfl_xor_sync(0xffffffffu, ps0, 2);
        ps1 += __shfl_xor_sync(0xffffffffu, ps1, 1);
        ps1 += __shfl_xor_sync(0xffffffffu, ps1, 2);
        l0r = l0r * cf0 + ps0;
        l1r = l1r * cf1 + ps1;
#pragma unroll
        for (int nt = 0; nt < 8; nt++) {
            o[nt][0] *= cf0; o[nt][1] *= cf0;
            o[nt][2] *= cf1; o[nt][3] *= cf1;
        }

        // wait for V(kt); barrier so ALL threads' copies are visible
        if (kt < 31) cp_wait<1>(); else cp_wait<0>();
        __syncthreads();

        // ---- O += P V ----
#pragma unroll
        for (int kc = 0; kc < 4; kc++) {
            uint32_t ph[4], pl[4];
            split2(s[2*kc][0],   s[2*kc][1],   ph[0], pl[0]);
            split2(s[2*kc][2],   s[2*kc][3],   ph[1], pl[1]);
            split2(s[2*kc+1][0], s[2*kc+1][1], ph[2], pl[2]);
            split2(s[2*kc+1][2], s[2*kc+1][3], ph[3], pl[3]);
            uint32_t vh[8][2], vl[8][2];
#pragma unroll
            for (int np = 0; np < 4; np++) {
                int row = kc * 16 + (lane & 15);
                int hc  = (np * 2 + (lane >> 4)) ^ (row & 7);
                uint32_t r0, r1, r2, r3;
                ldm_x4t(r0, r1, r2, r3, smem_u32(&sV[(row << 3) + hc]));
                vh[np*2+0][0] = r0; vh[np*2+0][1] = r1;
                vh[np*2+1][0] = r2; vh[np*2+1][1] = r3;
                ldm_x4t(r0, r1, r2, r3, smem_u32(&sV[512 + (row << 3) + hc]));
                vl[np*2+0][0] = r0; vl[np*2+0][1] = r1;
                vl[np*2+1][0] = r2; vl[np*2+1][1] = r3;
            }
#pragma unroll
            for (int nt = 0; nt < 8; nt++) {
                mma16816(o[nt], ph, vh[nt]);
                mma16816(o[nt], ph, vl[nt]);
                mma16816(o[nt], pl, vh[nt]);
            }
        }
        __syncthreads();   // protect sV/sK before next tile's issues
    }

    // ---- normalize + split-write y ----
    float inv0 = 1.f / l0r, inv1 = 1.f / l1r;
    int r = q0 + warp * 16 + (lane >> 2);
#pragma unroll
    for (int nt = 0; nt < 8; nt++) {
        int c = nt * 8 + (lane & 3) * 2;
        uint32_t hA, lA, hB, lB;
        split2(o[nt][0] * inv0, o[nt][1] * inv0, hA, lA);
        split2(o[nt][2] * inv1, o[nt][3] * inv1, hB, lB);
        size_t gA = (size_t)b * SS * DDIM + (size_t)r * DDIM + h * HDIM + c;
        size_t gB = gA + (size_t)8 * DDIM;
        *reinterpret_cast<uint32_t*>(&Yhi[gA]) = hA;
        *reinterpret_cast<uint32_t*>(&Ylo[gA]) = lA;
        *reinterpret_cast<uint32_t*>(&Yhi[gB]) = hB;
        *reinterpret_cast<uint32_t*>(&Ylo[gB]) = lB;
    }
}

// ---------------------------------------------------------------------------
// Launch
// ---------------------------------------------------------------------------
extern "C" void kernel_launch(void* const* d_in, const int* in_sizes, int n_in,
                              void* d_out, int out_size)
{
    const float* x  = (const float*)d_in[0];
    const float* Wq = (const float*)d_in[1];
    const float* Wk = (const float*)d_in[2];
    const float* Wv = (const float*)d_in[3];
    const float* Wo = (const float*)d_in[4];
    float* out = (float*)d_out;

    __nv_bfloat16 *xhi, *xlo, *wqhi, *wqlo, *wkhi, *wklo, *wvhi, *wvlo, *wohi, *wolo;
    __nv_bfloat16 *qhi, *qlo, *khi, *klo, *vhi, *vlo, *yhi, *ylo;
    cudaGetSymbolAddress((void**)&xhi, g_xhi);   cudaGetSymbolAddress((void**)&xlo, g_xlo);
    cudaGetSymbolAddress((void**)&wqhi, g_wqhi); cudaGetSymbolAddress((void**)&wqlo, g_wqlo);
    cudaGetSymbolAddress((void**)&wkhi, g_wkhi); cudaGetSymbolAddress((void**)&wklo, g_wklo);
    cudaGetSymbolAddress((void**)&wvhi, g_wvhi); cudaGetSymbolAddress((void**)&wvlo, g_wvlo);
    cudaGetSymbolAddress((void**)&wohi, g_wohi); cudaGetSymbolAddress((void**)&wolo, g_wolo);
    cudaGetSymbolAddress((void**)&qhi, g_qhi);   cudaGetSymbolAddress((void**)&qlo, g_qlo);
    cudaGetSymbolAddress((void**)&khi, g_khi);   cudaGetSymbolAddress((void**)&klo, g_klo);
    cudaGetSymbolAddress((void**)&vhi, g_vhi);   cudaGetSymbolAddress((void**)&vlo, g_vlo);
    cudaGetSymbolAddress((void**)&yhi, g_yhi);   cudaGetSymbolAddress((void**)&ylo, g_ylo);

    cudaFuncSetAttribute(gemm_bf16x3<true>,  cudaFuncAttributeMaxDynamicSharedMemorySize, G_SMEM_BYTES);
    cudaFuncSetAttribute(gemm_bf16x3<false>, cudaFuncAttributeMaxDynamicSharedMemorySize, G_SMEM_BYTES);
    cudaFuncSetAttribute(attn_bf16x3, cudaFuncAttributeMaxDynamicSharedMemorySize, ATTN_SMEM_BYTES);

    {
        int n4 = MTOT * DDIM / 4;
        split_kernel<<<(n4 + 255) / 256, 256>>>((const float4*)x,
                                                (__nv_bfloat162*)xhi, (__nv_bfloat162*)xlo, n4);
        int w4 = DDIM * DDIM / 4;
        split_kernel<<<(w4 + 255) / 256, 256>>>((const float4*)Wq,
                                                (__nv_bfloat162*)wqhi, (__nv_bfloat162*)wqlo, w4);
        split_kernel<<<(w4 + 255) / 256, 256>>>((const float4*)Wk,
                                                (__nv_bfloat162*)wkhi, (__nv_bfloat162*)wklo, w4);
        split_kernel<<<(w4 + 255) / 256, 256>>>((const float4*)Wv,
                                                (__nv_bfloat162*)wvhi, (__nv_bfloat162*)wvlo, w4);
        split_kernel<<<(w4 + 255) / 256, 256>>>((const float4*)Wo,
                                                (__nv_bfloat162*)wohi, (__nv_bfloat162*)wolo, w4);
    }

    dim3 gg(DDIM / 64, MTOT / 128);  // (16, 64)
    gemm_bf16x3<true><<<gg, 256, G_SMEM_BYTES>>>(xhi, xlo, wqhi, wqlo,
                                                 nullptr, qhi, qlo, MTOT, DDIM, DDIM);
    gemm_bf16x3<true><<<gg, 256, G_SMEM_BYTES>>>(xhi, xlo, wkhi, wklo,
                                                 nullptr, khi, klo, MTOT, DDIM, DDIM);
    gemm_bf16x3<true><<<gg, 256, G_SMEM_BYTES>>>(xhi, xlo, wvhi, wvlo,
                                                 nullptr, vhi, vlo, MTOT, DDIM, DDIM);

    dim3 ag(SS / 64, BB * NHEAD);  // (32, 64)
    attn_bf16x3<<<ag, 128, ATTN_SMEM_BYTES>>>(qhi, qlo, khi, klo, vhi, vlo, yhi, ylo);

    gemm_bf16x3<false><<<gg, 256, G_SMEM_BYTES>>>(yhi, ylo, wohi, wolo,
                                                  out, nullptr, nullptr, MTOT, DDIM, DDIM);
}